// round 15
// baseline (speedup 1.0000x reference)
#include <cuda_runtime.h>
#include <cuda_bf16.h>
#include <math.h>
#include <stdint.h>

// Problem dims (fixed)
#define NB   256
#define TT   128
#define DD   512
#define HH   1024
#define GG   4096
#define OUTD 128

typedef __nv_bfloat16 bf16;

// ---------------- device scratch (pre-swizzled tile blocks) ----------------
__device__ __align__(1024) char g_WhhT[(size_t)32 * 16 * 32768];
__device__ __align__(1024) char g_WihT[(size_t)32 * 8 * 32768];
__device__ __align__(1024) char g_xT[(size_t)256 * 8 * 32768];
__device__ __align__(1024) char g_hT[2][(size_t)4 * 16 * 16384];
__device__ __align__(1024) float g_xg[(size_t)TT * 4 * 32 * 8192];
__device__ float g_bias_r[GG];
__device__ float g_hlast[NB * HH];
__device__ float g_cbuf[NB * HH];

// ---------------- low-level helpers ----------------
__device__ __forceinline__ uint32_t smem_u32(const void* p) {
    uint32_t a;
    asm("{ .reg .u64 t; cvta.to.shared.u64 t, %1; cvt.u32.u64 %0, t; }" : "=r"(a) : "l"(p));
    return a;
}
__device__ __forceinline__ void ldsm4(uint32_t* r, uint32_t addr) {
    asm volatile("ldmatrix.sync.aligned.m8n8.x4.shared.b16 {%0,%1,%2,%3}, [%4];"
                 : "=r"(r[0]), "=r"(r[1]), "=r"(r[2]), "=r"(r[3]) : "r"(addr));
}
__device__ __forceinline__ void mma16816(float* d, const uint32_t* a, uint32_t b0, uint32_t b1) {
    asm volatile(
        "mma.sync.aligned.m16n8k16.row.col.f32.bf16.bf16.f32 "
        "{%0,%1,%2,%3}, {%4,%5,%6,%7}, {%8,%9}, {%0,%1,%2,%3};"
        : "+f"(d[0]), "+f"(d[1]), "+f"(d[2]), "+f"(d[3])
        : "r"(a[0]), "r"(a[1]), "r"(a[2]), "r"(a[3]), "r"(b0), "r"(b1));
}
__device__ __forceinline__ void bulk_g2s(uint32_t dst, const void* src, uint32_t bytes, uint32_t mb) {
    asm volatile("cp.async.bulk.shared::cta.global.mbarrier::complete_tx::bytes [%0], [%1], %2, [%3];"
                 :: "r"(dst), "l"(__cvta_generic_to_global(src)), "r"(bytes), "r"(mb) : "memory");
}
#define MBAR_INIT(mb, cnt) \
    asm volatile("mbarrier.init.shared.b64 [%0], %1;" :: "r"(mb), "r"(cnt) : "memory")
#define MBAR_EXPECT_TX(mb, bytes) \
    asm volatile("mbarrier.arrive.expect_tx.shared.b64 _, [%0], %1;" :: "r"(mb), "r"(bytes) : "memory")
#define MBAR_ARRIVE(mb) \
    asm volatile("mbarrier.arrive.shared.b64 _, [%0];" :: "r"(mb) : "memory")
#define MBAR_WAIT(mb, ph) do { \
    asm volatile("{\n\t.reg .pred P;\n\tW_%=:\n\t" \
                 "mbarrier.try_wait.parity.acquire.cta.shared::cta.b64 P, [%0], %1, 0x989680;\n\t" \
                 "@P bra.uni D_%=;\n\tbra.uni W_%=;\n\tD_%=:\n\t}" \
                 :: "r"(mb), "r"(ph) : "memory"); } while (0)

__device__ __forceinline__ uint32_t swz(int row, int j) {
    return (uint32_t)(row * 128 + ((j ^ (row & 7)) << 4));
}
__device__ __forceinline__ uint32_t tile_off8(int row, int col8) {
    // col8 = column aligned to 8; returns 16B-aligned offset
    return (uint32_t)(row * 128 + (((col8 >> 3) ^ (row & 7)) << 4));
}
__device__ __forceinline__ uint32_t pack2(bf16 a, bf16 b) {
    return (uint32_t)__bfloat16_as_ushort(a) | ((uint32_t)__bfloat16_as_ushort(b) << 16);
}

// ---------------- prep: build pre-swizzled tiles (vectorized 16B stores) ----------------
__global__ void prep_kernel(const float* __restrict__ x,
                            const float* __restrict__ Wih,
                            const float* __restrict__ Whh,
                            const float* __restrict__ bih,
                            const float* __restrict__ bhh) {
    int idx = blockIdx.x * blockDim.x + threadIdx.x;
    int stride = gridDim.x * blockDim.x;
    // W_ih: 8 cols per thread
    for (int i = idx; i < GG * DD / 8; i += stride) {
        int rn = i / (DD / 8), d0 = (i % (DD / 8)) * 8;
        int q = rn >> 2, p = rn & 3;
        const float* src = Wih + (size_t)(p * HH + q) * DD + d0;
        uint4 uh, ul;
        {
            bf16 h[8], l[8];
#pragma unroll
            for (int e = 0; e < 8; e++) {
                float w = src[e];
                h[e] = __float2bfloat16(w);
                l[e] = __float2bfloat16(w - __bfloat162float(h[e]));
            }
            uh = make_uint4(pack2(h[0], h[1]), pack2(h[2], h[3]), pack2(h[4], h[5]), pack2(h[6], h[7]));
            ul = make_uint4(pack2(l[0], l[1]), pack2(l[2], l[3]), pack2(l[4], l[5]), pack2(l[6], l[7]));
        }
        char* base = g_WihT + (((size_t)(rn >> 7) * 8 + (d0 >> 6)) * 32768);
        uint32_t so = tile_off8(rn & 127, d0 & 63);
        *(uint4*)(base + so) = uh;
        *(uint4*)(base + 16384 + so) = ul;
    }
    // W_hh
    for (int i = idx; i < GG * HH / 8; i += stride) {
        int rn = i / (HH / 8), d0 = (i % (HH / 8)) * 8;
        int q = rn >> 2, p = rn & 3;
        const float* src = Whh + (size_t)(p * HH + q) * HH + d0;
        uint4 uh, ul;
        {
            bf16 h[8], l[8];
#pragma unroll
            for (int e = 0; e < 8; e++) {
                float w = src[e];
                h[e] = __float2bfloat16(w);
                l[e] = __float2bfloat16(w - __bfloat162float(h[e]));
            }
            uh = make_uint4(pack2(h[0], h[1]), pack2(h[2], h[3]), pack2(h[4], h[5]), pack2(h[6], h[7]));
            ul = make_uint4(pack2(l[0], l[1]), pack2(l[2], l[3]), pack2(l[4], l[5]), pack2(l[6], l[7]));
        }
        char* base = g_WhhT + (((size_t)(rn >> 7) * 16 + (d0 >> 6)) * 32768);
        uint32_t so = tile_off8(rn & 127, d0 & 63);
        *(uint4*)(base + so) = uh;
        *(uint4*)(base + 16384 + so) = ul;
    }
    // x tiles
    for (size_t i = idx; i < (size_t)NB * TT * DD / 8; i += stride) {
        int m = (int)(i / (DD / 8)), d0 = (int)(i % (DD / 8)) * 8;
        const float* src = x + (size_t)m * DD + d0;
        uint4 uh, ul;
        {
            bf16 h[8], l[8];
#pragma unroll
            for (int e = 0; e < 8; e++) {
                float w = src[e];
                h[e] = __float2bfloat16(w);
                l[e] = __float2bfloat16(w - __bfloat162float(h[e]));
            }
            uh = make_uint4(pack2(h[0], h[1]), pack2(h[2], h[3]), pack2(h[4], h[5]), pack2(h[6], h[7]));
            ul = make_uint4(pack2(l[0], l[1]), pack2(l[2], l[3]), pack2(l[4], l[5]), pack2(l[6], l[7]));
        }
        char* base = g_xT + (((size_t)(m >> 7) * 8 + (d0 >> 6)) * 32768);
        uint32_t so = tile_off8(m & 127, d0 & 63);
        *(uint4*)(base + so) = uh;
        *(uint4*)(base + 16384 + so) = ul;
    }
    for (int i = idx; i < GG; i += stride) {
        int q = i >> 2, p = i & 3;
        g_bias_r[i] = bih[p * HH + q] + bhh[p * HH + q];
    }
    for (int i = idx; i < 4 * 16 * 16384 / 4; i += stride)
        reinterpret_cast<uint32_t*>(g_hT[0])[i] = 0;
    for (int i = idx; i < NB * HH; i += stride)
        g_cbuf[i] = 0.0f;
}

// ---------------- producer/consumer bulk-async HMMA mainloop ----------------
// NW = warps; KG K-groups of NW/KG warps (2M x 4N, warp tile (16*MF) x 32).
// Each group handles KSUB=4/KG K-substeps. B-frag reuse: bh -> pass0+pass2, bl -> pass1.
// Barriers at mbase: full[s] = +8*s, empty[s] = +8*(S+s) (NW arrivals).
template <int MF, int KG, int NW, int ABYTES, int S>
__device__ __forceinline__ void mma_mainloop_tma(
    const char* __restrict__ Ablk, const char* __restrict__ Bblk, int KC,
    uint32_t sbase, uint32_t mbase, float acc[MF][4][4]) {
    constexpr int STAGE = ABYTES + 32768;
    constexpr int KSUB = 4 / KG;
    constexpr int WPG = NW / KG;           // warps per K-group (8)
    const int tid = threadIdx.x;
    const int lane = tid & 31, wid = tid >> 5;
    const int kg = wid / WPG;
    const int w8 = wid % WPG;
    const int wm = (w8 >> 2) * (16 * MF);
    const int wn = (w8 & 3) * 32;
    const bool prod = (tid == 0);

    auto issue = [&](int ci) {
        int s = ci % S;
        uint32_t mb = mbase + 8u * s;
        uint32_t dst = sbase + (uint32_t)s * STAGE;
        MBAR_EXPECT_TX(mb, (uint32_t)(ABYTES + 32768));
        bulk_g2s(dst, Ablk + (size_t)ci * ABYTES, ABYTES, mb);
        bulk_g2s(dst + ABYTES, Bblk + (size_t)ci * 32768, 32768, mb);
    };

    if (prod) {
#pragma unroll
        for (int s = 0; s < S; s++)
            if (s < KC) issue(s);
    }

    for (int ci = 0; ci < KC; ci++) {
        const int s = ci % S;
        const uint32_t ph = (uint32_t)((ci / S) & 1);
        MBAR_WAIT(mbase + 8u * s, ph);              // full[s]
        uint32_t st = sbase + (uint32_t)s * STAGE;
        uint32_t sAh = st, sAl = st + ABYTES / 2;
        uint32_t sBh = st + ABYTES, sBl = st + ABYTES + 16384;
#pragma unroll
        for (int ks2 = 0; ks2 < KSUB; ks2++) {
            const int ks = kg * KSUB + ks2;
            uint32_t ah[MF][4], al[MF][4], b[2][4];
            const int j = ks * 2 + (lane >> 4);
#pragma unroll
            for (int mi = 0; mi < MF; mi++) {
                int row = wm + mi * 16 + (lane & 15);
                uint32_t so = swz(row, j);
                ldsm4(ah[mi], sAh + so);
                ldsm4(al[mi], sAl + so);
            }
            // B-hi fragments: pass0 (ah*bh) + pass2 (al*bh)
#pragma unroll
            for (int bi = 0; bi < 2; bi++) {
                int row = wn + bi * 16 + (lane & 15);
                ldsm4(b[bi], sBh + swz(row, j));
            }
#pragma unroll
            for (int mi = 0; mi < MF; mi++)
#pragma unroll
                for (int nf = 0; nf < 4; nf++)
                    mma16816(acc[mi][nf], ah[mi], b[nf >> 1][nf & 1], b[nf >> 1][(nf & 1) + 2]);
#pragma unroll
            for (int mi = 0; mi < MF; mi++)
#pragma unroll
                for (int nf = 0; nf < 4; nf++)
                    mma16816(acc[mi][nf], al[mi], b[nf >> 1][nf & 1], b[nf >> 1][(nf & 1) + 2]);
            // B-lo fragments (reuse regs): pass1 (ah*bl)
#pragma unroll
            for (int bi = 0; bi < 2; bi++) {
                int row = wn + bi * 16 + (lane & 15);
                ldsm4(b[bi], sBl + swz(row, j));
            }
#pragma unroll
            for (int mi = 0; mi < MF; mi++)
#pragma unroll
                for (int nf = 0; nf < 4; nf++)
                    mma16816(acc[mi][nf], ah[mi], b[nf >> 1][nf & 1], b[nf >> 1][(nf & 1) + 2]);
        }
        if (lane == 0) MBAR_ARRIVE(mbase + 8u * (S + s));   // empty[s]
        if (prod && ci + S < KC) {
            MBAR_WAIT(mbase + 8u * (S + s), ph);
            issue(ci + S);
        }
    }
    __syncthreads();
}

// ---------------- xgates: KG=1, 512 threads, MF=2, KC=8, S=3 ----------------
#define XG_MB_OFF (3 * (32768 + 32768))
#define XG_SMEM   (XG_MB_OFF + 128)

__global__ __launch_bounds__(512, 1)
void xgates_mma_kernel() {
    extern __shared__ __align__(1024) char smem[];
    const uint32_t sbase = smem_u32(smem);
    const uint32_t mbase = sbase + XG_MB_OFF;
    const int bn = blockIdx.x, bm = blockIdx.y;
    const int tid = threadIdx.x, lane = tid & 31, wid = tid >> 5;
    const int wm = (wid >> 2) * 32, wn = (wid & 3) * 32;

    if (tid == 0) {
#pragma unroll
        for (int s = 0; s < 3; s++) { MBAR_INIT(mbase + 8 * s, 1); MBAR_INIT(mbase + 8 * (3 + s), 16); }
    }
    __syncthreads();

    float acc[2][4][4];
#pragma unroll
    for (int i = 0; i < 2; i++)
#pragma unroll
        for (int j = 0; j < 4; j++)
#pragma unroll
            for (int k = 0; k < 4; k++) acc[i][j][k] = 0.0f;

    mma_mainloop_tma<2, 1, 16, 32768, 3>(
        g_xT + (size_t)bm * 8 * 32768, g_WihT + (size_t)bn * 8 * 32768, 8,
        sbase, mbase, acc);

#pragma unroll
    for (int mi = 0; mi < 2; mi++) {
#pragma unroll
        for (int nf = 0; nf < 4; nf++) {
            int m = bm * 128 + wm + mi * 16 + lane / 4;
            int n = bn * 128 + wn + nf * 8 + 2 * (lane & 3);
            float2 b2 = *reinterpret_cast<const float2*>(&g_bias_r[n]);
            int t0 = m % TT, b0 = m / TT;
            int m8 = m + 8;
            int t1 = m8 % TT, b1 = m8 / TT;
            size_t o0 = ((((size_t)t0 * 4 + (b0 >> 6)) * 32 + (n >> 7)) * 8192) + (b0 & 63) * 128 + (n & 127);
            size_t o1 = ((((size_t)t1 * 4 + (b1 >> 6)) * 32 + (n >> 7)) * 8192) + (b1 & 63) * 128 + (n & 127);
            *reinterpret_cast<float2*>(&g_xg[o0]) =
                make_float2(acc[mi][nf][0] + b2.x, acc[mi][nf][1] + b2.y);
            *reinterpret_cast<float2*>(&g_xg[o1]) =
                make_float2(acc[mi][nf][2] + b2.x, acc[mi][nf][3] + b2.y);
        }
    }
}

// ---------------- fused LSTM step: KG=4, 1024 threads ----------------
// 32 warps = 4 K-groups x 8 warps (2Mx4N, warp tile 32x32). KC=16, S=3.
// smem: 3*48KB stages + 32KB xg + 192 mbar
#define STEP_STAGE   (16384 + 32768)
#define STEP_XG_OFF  (3 * STEP_STAGE)
#define STEP_MB_OFF  (STEP_XG_OFF + 32768)
#define STEP_SMEM    (STEP_MB_OFF + 192)

__global__ __launch_bounds__(1024, 1)
void lstm_step_mma(int t, int buf) {
    extern __shared__ __align__(1024) char smem[];
    const uint32_t sbase = smem_u32(smem);
    const uint32_t mbase = sbase + STEP_MB_OFF;
    const int bn = blockIdx.x, bm = blockIdx.y;
    const int tid = threadIdx.x, lane = tid & 31, wid = tid >> 5;

    if (tid == 0) {
#pragma unroll
        for (int s = 0; s < 3; s++) { MBAR_INIT(mbase + 8 * s, 1); MBAR_INIT(mbase + 8 * (3 + s), 32); }
        MBAR_INIT(mbase + 64, 1);
    }
    __syncthreads();
    if (tid == 0) {
        MBAR_EXPECT_TX(mbase + 64, 32768u);
        bulk_g2s(sbase + STEP_XG_OFF,
                 (const char*)g_xg + (((size_t)t * 4 + bm) * 32 + bn) * 32768,
                 32768u, mbase + 64);
    }

    float acc[2][4][4];
#pragma unroll
    for (int i = 0; i < 2; i++)
#pragma unroll
        for (int j = 0; j < 4; j++)
#pragma unroll
            for (int k = 0; k < 4; k++) acc[i][j][k] = 0.0f;

    mma_mainloop_tma<2, 4, 32, 16384, 3>(
        g_hT[buf] + (size_t)bm * 16 * 16384, g_WhhT + (size_t)bn * 16 * 32768, 16,
        sbase, mbase, acc);

    // stage 4 K-groups' partial gates: gsm[4][64][128] = 128KB (stage area is 144KB)
    float* gsm = reinterpret_cast<float*>(smem);
    {
        const int kg = wid >> 3, w8 = wid & 7;
        const int wm = (w8 >> 2) * 32, wn = (w8 & 3) * 32;
#pragma unroll
        for (int mi = 0; mi < 2; mi++) {
#pragma unroll
            for (int nf = 0; nf < 4; nf++) {
                int r0 = wm + mi * 16 + lane / 4;
                int col = wn + nf * 8 + 2 * (lane & 3);
                *reinterpret_cast<float2*>(&gsm[kg * 8192 + r0 * 128 + col]) =
                    make_float2(acc[mi][nf][0], acc[mi][nf][1]);
                *reinterpret_cast<float2*>(&gsm[kg * 8192 + (r0 + 8) * 128 + col]) =
                    make_float2(acc[mi][nf][2], acc[mi][nf][3]);
            }
        }
    }
    MBAR_WAIT(mbase + 64, 0u);
    __syncthreads();

    const float* xgsm = reinterpret_cast<const float*>(smem + STEP_XG_OFF);
    char* hout = g_hT[buf ^ 1];
#pragma unroll
    for (int it = 0; it < 2; it++) {
        int idx = it * 1024 + tid;
        int m = idx >> 5, q = idx & 31;
        int mg = bm * 64 + m;
        int qg = bn * 32 + q;
        float4 g0 = *reinterpret_cast<const float4*>(&gsm[m * 128 + q * 4]);
        float4 g1 = *reinterpret_cast<const float4*>(&gsm[8192 + m * 128 + q * 4]);
        float4 g2 = *reinterpret_cast<const float4*>(&gsm[16384 + m * 128 + q * 4]);
        float4 g3 = *reinterpret_cast<const float4*>(&gsm[24576 + m * 128 + q * 4]);
        float4 xv = *reinterpret_cast<const float4*>(&xgsm[m * 128 + q * 4]);
        float a0 = (g0.x + g1.x) + (g2.x + g3.x) + xv.x;
        float a1 = (g0.y + g1.y) + (g2.y + g3.y) + xv.y;
        float a2 = (g0.z + g1.z) + (g2.z + g3.z) + xv.z;
        float a3 = (g0.w + g1.w) + (g2.w + g3.w) + xv.w;
        float ig = 1.0f / (1.0f + expf(-a0));
        float fg = 1.0f / (1.0f + expf(-a1));
        float gg = tanhf(a2);
        float og = 1.0f / (1.0f + expf(-a3));
        float cn = fg * g_cbuf[mg * HH + qg] + ig * gg;
        g_cbuf[mg * HH + qg] = cn;
        float hv = og * tanhf(cn);
        g_hlast[mg * HH + qg] = hv;
        bf16 hib = __float2bfloat16(hv);
        bf16 lob = __float2bfloat16(hv - __bfloat162float(hib));
        char* base = hout + ((size_t)(bm * 16 + (qg >> 6))) * 16384;
        uint32_t so = (uint32_t)(m * 128 + ((((qg & 63) >> 3) ^ (m & 7)) << 4) + (qg & 7) * 2);
        *(bf16*)(base + so) = hib;
        *(bf16*)(base + 8192 + so) = lob;
    }
}

// ---------------- fp32 SIMT GEMM (head only) ----------------
#define EPI_BIAS 0
#define EPI_RELU 1
template <int BM, int BN, int BK, int TM, int TN, int EPI>
__global__ void gemm_bias_kernel(const float* __restrict__ A,
                                 const float* __restrict__ B,
                                 const float* __restrict__ bias,
                                 float* __restrict__ C,
                                 int M, int N, int K) {
    constexpr int NT = (BM * BN) / (TM * TN);
    __shared__ float As[BK][BM];
    __shared__ float Bs[BK][BN];
    const int tid = threadIdx.x;
    const int bn = blockIdx.x, bm = blockIdx.y;
    const int tx = tid % (BN / TN);
    const int ty = tid / (BN / TN);
    const float* Ab = A + (size_t)bm * BM * K;
    const float* Bb = B + (size_t)bn * BN * K;
    float acc[TM][TN];
#pragma unroll
    for (int i = 0; i < TM; i++)
#pragma unroll
        for (int j = 0; j < TN; j++) acc[i][j] = 0.0f;
    for (int k0 = 0; k0 < K; k0 += BK) {
        constexpr int A4 = BM * BK / 4;
        constexpr int B4 = BN * BK / 4;
#pragma unroll
        for (int i0 = 0; i0 < A4; i0 += NT) {
            int i = i0 + tid;
            int r = i / (BK / 4), c = (i % (BK / 4)) * 4;
            float4 v = *reinterpret_cast<const float4*>(Ab + (size_t)r * K + k0 + c);
            As[c + 0][r] = v.x; As[c + 1][r] = v.y; As[c + 2][r] = v.z; As[c + 3][r] = v.w;
        }
#pragma unroll
        for (int i0 = 0; i0 < B4; i0 += NT) {
            int i = i0 + tid;
            int r = i / (BK / 4), c = (i % (BK / 4)) * 4;
            float4 v = *reinterpret_cast<const float4*>(Bb + (size_t)r * K + k0 + c);
            Bs[c + 0][r] = v.x; Bs[c + 1][r] = v.y; Bs[c + 2][r] = v.z; Bs[c + 3][r] = v.w;
        }
        __syncthreads();
#pragma unroll
        for (int k = 0; k < BK; k++) {
            float ra[TM], rb[TN];
#pragma unroll
            for (int i = 0; i < TM; i += 4) {
                float4 v = *reinterpret_cast<const float4*>(&As[k][ty * TM + i]);
                ra[i] = v.x; ra[i + 1] = v.y; ra[i + 2] = v.z; ra[i + 3] = v.w;
            }
#pragma unroll
            for (int j = 0; j < TN; j += 4) {
                float4 v = *reinterpret_cast<const float4*>(&Bs[k][tx * TN + j]);
                rb[j] = v.x; rb[j + 1] = v.y; rb[j + 2] = v.z; rb[j + 3] = v.w;
            }
#pragma unroll
            for (int i = 0; i < TM; i++)
#pragma unroll
                for (int j = 0; j < TN; j++) acc[i][j] += ra[i] * rb[j];
        }
        __syncthreads();
    }
#pragma unroll
    for (int i = 0; i < TM; i++) {
        int m = bm * BM + ty * TM + i;
#pragma unroll
        for (int j = 0; j < TN; j++) {
            int n = bn * BN + tx * TN + j;
            float v = acc[i][j] + bias[n];
            if (EPI == EPI_RELU) v = fmaxf(v, 0.0f);
            C[(size_t)m * N + n] = v;
        }
    }
}

// ---------------- host ----------------
extern "C" void kernel_launch(void* const* d_in, const int* in_sizes, int n_in,
                              void* d_out, int out_size) {
    const float* x    = (const float*)d_in[0];
    const float* W_ih = (const float*)d_in[1];
    const float* W_hh = (const float*)d_in[2];
    const float* b_ih = (const float*)d_in[3];
    const float* b_hh = (const float*)d_in[4];
    const float* W1   = (const float*)d_in[5];
    const float* b1   = (const float*)d_in[6];
    const float* W2   = (const float*)d_in[7];
    const float* b2   = (const float*)d_in[8];
    float* out = (float*)d_out;

    float* p_hlast;
    cudaGetSymbolAddress((void**)&p_hlast, g_hlast);

    static int attr_set = 0;
    if (!attr_set) {
        cudaFuncSetAttribute(lstm_step_mma, cudaFuncAttributeMaxDynamicSharedMemorySize, STEP_SMEM);
        cudaFuncSetAttribute(xgates_mma_kernel, cudaFuncAttributeMaxDynamicSharedMemorySize, XG_SMEM);
        attr_set = 1;
    }

    // 1) pre-swizzled tiles for W_ih / W_hh / x; bias; zero state
    prep_kernel<<<1024, 256>>>(x, W_ih, W_hh, b_ih, b_hh);

    // 2) x_gates via HMMA + bulk-async, written in xg tile blocks
    xgates_mma_kernel<<<dim3(GG / 128, (NB * TT) / 128), 512, XG_SMEM>>>();

    // 3) 128 recurrent steps (1024 threads, 4 K-groups)
    for (int t = 0; t < TT; t++)
        lstm_step_mma<<<dim3(GG / 128, NB / 64), 1024, STEP_SMEM>>>(t, t & 1);

    // 4) head (fp32 SIMT)
    float* pre_out = out + NB * OUTD;
    gemm_bias_kernel<64, 128, 16, 4, 8, EPI_RELU>
        <<<dim3(HH / 128, NB / 64), 256>>>(p_hlast, W1, b1, pre_out, NB, HH, HH);
    gemm_bias_kernel<64, 128, 16, 4, 8, EPI_BIAS>
        <<<dim3(OUTD / 128, NB / 64), 256>>>(pre_out, W2, b2, out, NB, OUTD, HH);
}

// round 17
// speedup vs baseline: 1.0720x; 1.0720x over previous
#include <cuda_runtime.h>
#include <cuda_bf16.h>
#include <math.h>
#include <stdint.h>

// Problem dims (fixed)
#define NB   256
#define TT   128
#define DD   512
#define HH   1024
#define GG   4096
#define OUTD 128

typedef __nv_bfloat16 bf16;

// ---------------- device scratch (pre-swizzled tile blocks) ----------------
__device__ __align__(1024) char g_WhhT[(size_t)32 * 16 * 32768];
__device__ __align__(1024) char g_WihT[(size_t)32 * 8 * 32768];
__device__ __align__(1024) char g_xT[(size_t)256 * 8 * 32768];
__device__ __align__(1024) char g_hT[2][(size_t)4 * 16 * 16384];
__device__ __align__(1024) float g_xg[(size_t)TT * 4 * 32 * 8192];
__device__ float g_bias_r[GG];
__device__ float g_hlast[NB * HH];
__device__ float g_cbuf[NB * HH];
__device__ int g_sync_count;   // monotonic ticket counter (reset only by prep)

// ---------------- low-level helpers ----------------
__device__ __forceinline__ uint32_t smem_u32(const void* p) {
    uint32_t a;
    asm("{ .reg .u64 t; cvta.to.shared.u64 t, %1; cvt.u32.u64 %0, t; }" : "=r"(a) : "l"(p));
    return a;
}
__device__ __forceinline__ void ldsm4(uint32_t* r, uint32_t addr) {
    asm volatile("ldmatrix.sync.aligned.m8n8.x4.shared.b16 {%0,%1,%2,%3}, [%4];"
                 : "=r"(r[0]), "=r"(r[1]), "=r"(r[2]), "=r"(r[3]) : "r"(addr));
}
__device__ __forceinline__ void mma16816(float* d, const uint32_t* a, uint32_t b0, uint32_t b1) {
    asm volatile(
        "mma.sync.aligned.m16n8k16.row.col.f32.bf16.bf16.f32 "
        "{%0,%1,%2,%3}, {%4,%5,%6,%7}, {%8,%9}, {%0,%1,%2,%3};"
        : "+f"(d[0]), "+f"(d[1]), "+f"(d[2]), "+f"(d[3])
        : "r"(a[0]), "r"(a[1]), "r"(a[2]), "r"(a[3]), "r"(b0), "r"(b1));
}
__device__ __forceinline__ void bulk_g2s(uint32_t dst, const void* src, uint32_t bytes, uint32_t mb) {
    asm volatile("cp.async.bulk.shared::cta.global.mbarrier::complete_tx::bytes [%0], [%1], %2, [%3];"
                 :: "r"(dst), "l"(__cvta_generic_to_global(src)), "r"(bytes), "r"(mb) : "memory");
}
#define MBAR_INIT(mb, cnt) \
    asm volatile("mbarrier.init.shared.b64 [%0], %1;" :: "r"(mb), "r"(cnt) : "memory")
#define MBAR_EXPECT_TX(mb, bytes) \
    asm volatile("mbarrier.arrive.expect_tx.shared.b64 _, [%0], %1;" :: "r"(mb), "r"(bytes) : "memory")
#define MBAR_ARRIVE(mb) \
    asm volatile("mbarrier.arrive.shared.b64 _, [%0];" :: "r"(mb) : "memory")
#define MBAR_WAIT(mb, ph) do { \
    asm volatile("{\n\t.reg .pred P;\n\tW_%=:\n\t" \
                 "mbarrier.try_wait.parity.acquire.cta.shared::cta.b64 P, [%0], %1, 0x989680;\n\t" \
                 "@P bra.uni D_%=;\n\tbra.uni W_%=;\n\tD_%=:\n\t}" \
                 :: "r"(mb), "r"(ph) : "memory"); } while (0)

__device__ __forceinline__ uint32_t swz(int row, int j) {
    return (uint32_t)(row * 128 + ((j ^ (row & 7)) << 4));
}
__device__ __forceinline__ uint32_t tile_off8(int row, int col8) {
    return (uint32_t)(row * 128 + (((col8 >> 3) ^ (row & 7)) << 4));
}
__device__ __forceinline__ uint32_t pack2(bf16 a, bf16 b) {
    return (uint32_t)__bfloat16_as_ushort(a) | ((uint32_t)__bfloat16_as_ushort(b) << 16);
}

// ---------------- prep: build pre-swizzled tiles (vectorized) ----------------
__global__ void prep_kernel(const float* __restrict__ x,
                            const float* __restrict__ Wih,
                            const float* __restrict__ Whh,
                            const float* __restrict__ bih,
                            const float* __restrict__ bhh) {
    int idx = blockIdx.x * blockDim.x + threadIdx.x;
    int stride = gridDim.x * blockDim.x;
    if (idx == 0) g_sync_count = 0;
    for (int i = idx; i < GG * DD / 8; i += stride) {
        int rn = i / (DD / 8), d0 = (i % (DD / 8)) * 8;
        int q = rn >> 2, p = rn & 3;
        const float* src = Wih + (size_t)(p * HH + q) * DD + d0;
        bf16 h[8], l[8];
#pragma unroll
        for (int e = 0; e < 8; e++) {
            float w = src[e];
            h[e] = __float2bfloat16(w);
            l[e] = __float2bfloat16(w - __bfloat162float(h[e]));
        }
        uint4 uh = make_uint4(pack2(h[0], h[1]), pack2(h[2], h[3]), pack2(h[4], h[5]), pack2(h[6], h[7]));
        uint4 ul = make_uint4(pack2(l[0], l[1]), pack2(l[2], l[3]), pack2(l[4], l[5]), pack2(l[6], l[7]));
        char* base = g_WihT + (((size_t)(rn >> 7) * 8 + (d0 >> 6)) * 32768);
        uint32_t so = tile_off8(rn & 127, d0 & 63);
        *(uint4*)(base + so) = uh;
        *(uint4*)(base + 16384 + so) = ul;
    }
    for (int i = idx; i < GG * HH / 8; i += stride) {
        int rn = i / (HH / 8), d0 = (i % (HH / 8)) * 8;
        int q = rn >> 2, p = rn & 3;
        const float* src = Whh + (size_t)(p * HH + q) * HH + d0;
        bf16 h[8], l[8];
#pragma unroll
        for (int e = 0; e < 8; e++) {
            float w = src[e];
            h[e] = __float2bfloat16(w);
            l[e] = __float2bfloat16(w - __bfloat162float(h[e]));
        }
        uint4 uh = make_uint4(pack2(h[0], h[1]), pack2(h[2], h[3]), pack2(h[4], h[5]), pack2(h[6], h[7]));
        uint4 ul = make_uint4(pack2(l[0], l[1]), pack2(l[2], l[3]), pack2(l[4], l[5]), pack2(l[6], l[7]));
        char* base = g_WhhT + (((size_t)(rn >> 7) * 16 + (d0 >> 6)) * 32768);
        uint32_t so = tile_off8(rn & 127, d0 & 63);
        *(uint4*)(base + so) = uh;
        *(uint4*)(base + 16384 + so) = ul;
    }
    for (size_t i = idx; i < (size_t)NB * TT * DD / 8; i += stride) {
        int m = (int)(i / (DD / 8)), d0 = (int)(i % (DD / 8)) * 8;
        const float* src = x + (size_t)m * DD + d0;
        bf16 h[8], l[8];
#pragma unroll
        for (int e = 0; e < 8; e++) {
            float w = src[e];
            h[e] = __float2bfloat16(w);
            l[e] = __float2bfloat16(w - __bfloat162float(h[e]));
        }
        uint4 uh = make_uint4(pack2(h[0], h[1]), pack2(h[2], h[3]), pack2(h[4], h[5]), pack2(h[6], h[7]));
        uint4 ul = make_uint4(pack2(l[0], l[1]), pack2(l[2], l[3]), pack2(l[4], l[5]), pack2(l[6], l[7]));
        char* base = g_xT + (((size_t)(m >> 7) * 8 + (d0 >> 6)) * 32768);
        uint32_t so = tile_off8(m & 127, d0 & 63);
        *(uint4*)(base + so) = uh;
        *(uint4*)(base + 16384 + so) = ul;
    }
    for (int i = idx; i < GG; i += stride) {
        int q = i >> 2, p = i & 3;
        g_bias_r[i] = bih[p * HH + q] + bhh[p * HH + q];
    }
    for (int i = idx; i < 4 * 16 * 16384 / 4; i += stride)
        reinterpret_cast<uint32_t*>(g_hT[0])[i] = 0;
    for (int i = idx; i < NB * HH; i += stride)
        g_cbuf[i] = 0.0f;
}

// ---------------- bulk-async HMMA mainloop template (xgates only) ----------------
template <int MF, int KG, int NW, int ABYTES, int S>
__device__ __forceinline__ void mma_mainloop_tma(
    const char* __restrict__ Ablk, const char* __restrict__ Bblk, int KC,
    uint32_t sbase, uint32_t mbase, float acc[MF][4][4]) {
    constexpr int STAGE = ABYTES + 32768;
    constexpr int KSUB = 4 / KG;
    constexpr int WPG = NW / KG;
    const int tid = threadIdx.x;
    const int lane = tid & 31, wid = tid >> 5;
    const int kg = wid / WPG;
    const int w8 = wid % WPG;
    const int wm = (w8 >> 2) * (16 * MF);
    const int wn = (w8 & 3) * 32;
    const bool prod = (tid == 0);

    auto issue = [&](int ci) {
        int s = ci % S;
        uint32_t mb = mbase + 8u * s;
        uint32_t dst = sbase + (uint32_t)s * STAGE;
        MBAR_EXPECT_TX(mb, (uint32_t)(ABYTES + 32768));
        bulk_g2s(dst, Ablk + (size_t)ci * ABYTES, ABYTES, mb);
        bulk_g2s(dst + ABYTES, Bblk + (size_t)ci * 32768, 32768, mb);
    };

    if (prod) {
#pragma unroll
        for (int s = 0; s < S; s++)
            if (s < KC) issue(s);
    }

    for (int ci = 0; ci < KC; ci++) {
        const int s = ci % S;
        const uint32_t ph = (uint32_t)((ci / S) & 1);
        MBAR_WAIT(mbase + 8u * s, ph);
        uint32_t st = sbase + (uint32_t)s * STAGE;
        uint32_t sAh = st, sAl = st + ABYTES / 2;
        uint32_t sBh = st + ABYTES, sBl = st + ABYTES + 16384;
#pragma unroll
        for (int ks2 = 0; ks2 < KSUB; ks2++) {
            const int ks = kg * KSUB + ks2;
            uint32_t ah[MF][4], al[MF][4], bh[2][4], bl[2][4];
            const int j = ks * 2 + (lane >> 4);
#pragma unroll
            for (int mi = 0; mi < MF; mi++) {
                int row = wm + mi * 16 + (lane & 15);
                uint32_t so = swz(row, j);
                ldsm4(ah[mi], sAh + so);
                ldsm4(al[mi], sAl + so);
            }
#pragma unroll
            for (int bi = 0; bi < 2; bi++) {
                int row = wn + bi * 16 + (lane & 15);
                uint32_t so = swz(row, j);
                ldsm4(bh[bi], sBh + so);
                ldsm4(bl[bi], sBl + so);
            }
#pragma unroll
            for (int mi = 0; mi < MF; mi++)
#pragma unroll
                for (int nf = 0; nf < 4; nf++)
                    mma16816(acc[mi][nf], ah[mi], bh[nf >> 1][nf & 1], bh[nf >> 1][(nf & 1) + 2]);
#pragma unroll
            for (int mi = 0; mi < MF; mi++)
#pragma unroll
                for (int nf = 0; nf < 4; nf++)
                    mma16816(acc[mi][nf], ah[mi], bl[nf >> 1][nf & 1], bl[nf >> 1][(nf & 1) + 2]);
#pragma unroll
            for (int mi = 0; mi < MF; mi++)
#pragma unroll
                for (int nf = 0; nf < 4; nf++)
                    mma16816(acc[mi][nf], al[mi], bh[nf >> 1][nf & 1], bh[nf >> 1][(nf & 1) + 2]);
        }
        if (lane == 0) MBAR_ARRIVE(mbase + 8u * (S + s));
        if (prod && ci + S < KC) {
            MBAR_WAIT(mbase + 8u * (S + s), ph);
            issue(ci + S);
        }
    }
    __syncthreads();
}

// ---------------- xgates ----------------
#define XG_MB_OFF (3 * (32768 + 32768))
#define XG_SMEM   (XG_MB_OFF + 128)

__global__ __launch_bounds__(512, 1)
void xgates_mma_kernel() {
    extern __shared__ __align__(1024) char smem[];
    const uint32_t sbase = smem_u32(smem);
    const uint32_t mbase = sbase + XG_MB_OFF;
    const int bn = blockIdx.x, bm = blockIdx.y;
    const int tid = threadIdx.x, lane = tid & 31, wid = tid >> 5;
    const int wm = (wid >> 2) * 32, wn = (wid & 3) * 32;

    if (tid == 0) {
#pragma unroll
        for (int s = 0; s < 3; s++) { MBAR_INIT(mbase + 8 * s, 1); MBAR_INIT(mbase + 8 * (3 + s), 16); }
    }
    __syncthreads();

    float acc[2][4][4];
#pragma unroll
    for (int i = 0; i < 2; i++)
#pragma unroll
        for (int j = 0; j < 4; j++)
#pragma unroll
            for (int k = 0; k < 4; k++) acc[i][j][k] = 0.0f;

    mma_mainloop_tma<2, 1, 16, 32768, 3>(
        g_xT + (size_t)bm * 8 * 32768, g_WihT + (size_t)bn * 8 * 32768, 8,
        sbase, mbase, acc);

#pragma unroll
    for (int mi = 0; mi < 2; mi++) {
#pragma unroll
        for (int nf = 0; nf < 4; nf++) {
            int m = bm * 128 + wm + mi * 16 + lane / 4;
            int n = bn * 128 + wn + nf * 8 + 2 * (lane & 3);
            float2 b2 = *reinterpret_cast<const float2*>(&g_bias_r[n]);
            int t0 = m % TT, b0 = m / TT;
            int m8 = m + 8;
            int t1 = m8 % TT, b1 = m8 / TT;
            size_t o0 = ((((size_t)t0 * 4 + (b0 >> 6)) * 32 + (n >> 7)) * 8192) + (b0 & 63) * 128 + (n & 127);
            size_t o1 = ((((size_t)t1 * 4 + (b1 >> 6)) * 32 + (n >> 7)) * 8192) + (b1 & 63) * 128 + (n & 127);
            *reinterpret_cast<float2*>(&g_xg[o0]) =
                make_float2(acc[mi][nf][0] + b2.x, acc[mi][nf][1] + b2.y);
            *reinterpret_cast<float2*>(&g_xg[o1]) =
                make_float2(acc[mi][nf][2] + b2.x, acc[mi][nf][3] + b2.y);
        }
    }
}

// ---------------- persistent LSTM: all 128 steps in one launch ----------------
// 128 CTAs (32 bn x 4 bm), 512 threads, KG=2 (2 K-groups x 8 warps).
// B pipeline (3 stages) streams continuously across steps; A pipeline 2 stages;
// gsm + xg in dedicated smem. Grid barrier = monotonic ticket counter (no reset).
#define P_OFF_B   0
#define P_OFF_A   98304
#define P_OFF_GSM 131072
#define P_OFF_XG  196608
#define P_OFF_MB  229376
#define P_SMEM    (229376 + 128)
// barriers: Bfull[s]=+8s (s<3), Bempty[s]=+24+8s, Afull[s]=+48+8s (s<2),
//           Aempty[s]=+64+8s, xg=+80

__global__ __launch_bounds__(512, 1)
void lstm_persistent() {
    extern __shared__ __align__(1024) char smem[];
    const uint32_t sbase = smem_u32(smem);
    const uint32_t mb = sbase + P_OFF_MB;
    const int bn = blockIdx.x, bm = blockIdx.y;
    const int tid = threadIdx.x, lane = tid & 31, wid = tid >> 5;
    const int kg = wid >> 3, w8 = wid & 7;
    const int wm = (w8 >> 2) * 32, wn = (w8 & 3) * 32;
    const bool prod = (tid == 0);
    const char* Bbase = g_WhhT + (size_t)bn * 16 * 32768;

    if (tid == 0) {
#pragma unroll
        for (int s = 0; s < 3; s++) { MBAR_INIT(mb + 8 * s, 1); MBAR_INIT(mb + 24 + 8 * s, 16); }
#pragma unroll
        for (int s = 0; s < 2; s++) { MBAR_INIT(mb + 48 + 8 * s, 1); MBAR_INIT(mb + 64 + 8 * s, 16); }
        MBAR_INIT(mb + 80, 1);
    }
    __syncthreads();

    auto issueB = [&](int gc) {
        int s = gc % 3;
        MBAR_EXPECT_TX(mb + 8u * s, 32768u);
        bulk_g2s(sbase + P_OFF_B + (uint32_t)s * 32768, Bbase + (size_t)(gc & 15) * 32768,
                 32768u, mb + 8u * s);
    };
    auto issueA = [&](int gc, const char* Abase) {
        int s = gc & 1;
        MBAR_EXPECT_TX(mb + 48 + 8u * s, 16384u);
        bulk_g2s(sbase + P_OFF_A + (uint32_t)s * 16384, Abase + (size_t)(gc & 15) * 16384,
                 16384u, mb + 48 + 8u * s);
    };
    auto issueXG = [&](int t) {
        MBAR_EXPECT_TX(mb + 80, 32768u);
        bulk_g2s(sbase + P_OFF_XG,
                 (const char*)g_xg + (((size_t)t * 4 + bm) * 32 + bn) * 32768, 32768u, mb + 80);
    };

    if (prod) {
        issueB(0); issueB(1); issueB(2);
        const char* A0 = g_hT[0] + (size_t)bm * 16 * 16384;
        issueA(0, A0); issueA(1, A0);
        issueXG(0);
    }

    for (int t = 0; t < TT; t++) {
        const char* Abase = g_hT[t & 1] + (size_t)bm * 16 * 16384;
        char* hout = g_hT[(t & 1) ^ 1];

        float acc[2][4][4];
#pragma unroll
        for (int i = 0; i < 2; i++)
#pragma unroll
            for (int j = 0; j < 4; j++)
#pragma unroll
                for (int k = 0; k < 4; k++) acc[i][j][k] = 0.0f;

        for (int ci = 0; ci < 16; ci++) {
            const int gc = t * 16 + ci;
            MBAR_WAIT(mb + 48 + 8u * (gc & 1), (uint32_t)((gc >> 1) & 1));
            MBAR_WAIT(mb + 8u * (gc % 3), (uint32_t)((gc / 3) & 1));
            uint32_t sA = sbase + P_OFF_A + (uint32_t)(gc & 1) * 16384;
            uint32_t sAh = sA, sAl = sA + 8192;
            uint32_t sB = sbase + P_OFF_B + (uint32_t)(gc % 3) * 32768;
            uint32_t sBh = sB, sBl = sB + 16384;
#pragma unroll
            for (int ks2 = 0; ks2 < 2; ks2++) {
                const int ks = kg * 2 + ks2;
                uint32_t ah[2][4], al[2][4], bh[2][4], bl[2][4];
                const int j = ks * 2 + (lane >> 4);
#pragma unroll
                for (int mi = 0; mi < 2; mi++) {
                    int row = wm + mi * 16 + (lane & 15);
                    uint32_t so = swz(row, j);
                    ldsm4(ah[mi], sAh + so);
                    ldsm4(al[mi], sAl + so);
                }
#pragma unroll
                for (int bi = 0; bi < 2; bi++) {
                    int row = wn + bi * 16 + (lane & 15);
                    uint32_t so = swz(row, j);
                    ldsm4(bh[bi], sBh + so);
                    ldsm4(bl[bi], sBl + so);
                }
#pragma unroll
                for (int mi = 0; mi < 2; mi++)
#pragma unroll
                    for (int nf = 0; nf < 4; nf++)
                        mma16816(acc[mi][nf], ah[mi], bh[nf >> 1][nf & 1], bh[nf >> 1][(nf & 1) + 2]);
#pragma unroll
                for (int mi = 0; mi < 2; mi++)
#pragma unroll
                    for (int nf = 0; nf < 4; nf++)
                        mma16816(acc[mi][nf], ah[mi], bl[nf >> 1][nf & 1], bl[nf >> 1][(nf & 1) + 2]);
#pragma unroll
                for (int mi = 0; mi < 2; mi++)
#pragma unroll
                    for (int nf = 0; nf < 4; nf++)
                        mma16816(acc[mi][nf], al[mi], bh[nf >> 1][nf & 1], bh[nf >> 1][(nf & 1) + 2]);
            }
            if (lane == 0) {
                MBAR_ARRIVE(mb + 64 + 8u * (gc & 1));
                MBAR_ARRIVE(mb + 24 + 8u * (gc % 3));
            }
            if (prod) {
                int nbk = gc + 3;
                if (nbk < TT * 16) {
                    MBAR_WAIT(mb + 24 + 8u * (gc % 3), (uint32_t)((gc / 3) & 1));
                    issueB(nbk);
                }
                if (ci + 2 < 16) {
                    MBAR_WAIT(mb + 64 + 8u * (gc & 1), (uint32_t)((gc >> 1) & 1));
                    issueA(gc + 2, Abase);
                }
            }
        }

        // epilogue: stage both K-groups' partial gates, then cell update
        float* gsm = reinterpret_cast<float*>(smem + P_OFF_GSM);
#pragma unroll
        for (int mi = 0; mi < 2; mi++) {
#pragma unroll
            for (int nf = 0; nf < 4; nf++) {
                int r0 = wm + mi * 16 + lane / 4;
                int col = wn + nf * 8 + 2 * (lane & 3);
                *reinterpret_cast<float2*>(&gsm[kg * 8192 + r0 * 128 + col]) =
                    make_float2(acc[mi][nf][0], acc[mi][nf][1]);
                *reinterpret_cast<float2*>(&gsm[kg * 8192 + (r0 + 8) * 128 + col]) =
                    make_float2(acc[mi][nf][2], acc[mi][nf][3]);
            }
        }
        __syncthreads();
        MBAR_WAIT(mb + 80, (uint32_t)(t & 1));
        const float* xgsm = reinterpret_cast<const float*>(smem + P_OFF_XG);
#pragma unroll
        for (int it = 0; it < 4; it++) {
            int idx = it * 512 + tid;
            int m = idx >> 5, q = idx & 31;
            int mg = bm * 64 + m;
            int qg = bn * 32 + q;
            float4 g0 = *reinterpret_cast<const float4*>(&gsm[m * 128 + q * 4]);
            float4 g1 = *reinterpret_cast<const float4*>(&gsm[8192 + m * 128 + q * 4]);
            float4 xv = *reinterpret_cast<const float4*>(&xgsm[m * 128 + q * 4]);
            float a0 = g0.x + g1.x + xv.x;
            float a1 = g0.y + g1.y + xv.y;
            float a2 = g0.z + g1.z + xv.z;
            float a3 = g0.w + g1.w + xv.w;
            float ig = 1.0f / (1.0f + expf(-a0));
            float fg = 1.0f / (1.0f + expf(-a1));
            float gg = tanhf(a2);
            float og = 1.0f / (1.0f + expf(-a3));
            float cn = fg * g_cbuf[mg * HH + qg] + ig * gg;
            g_cbuf[mg * HH + qg] = cn;
            float hv = og * tanhf(cn);
            if (t == TT - 1) g_hlast[mg * HH + qg] = hv;
            bf16 hib = __float2bfloat16(hv);
            bf16 lob = __float2bfloat16(hv - __bfloat162float(hib));
            char* base = hout + ((size_t)(bm * 16 + (qg >> 6))) * 16384;
            uint32_t so = (uint32_t)(m * 128 + ((((qg & 63) >> 3) ^ (m & 7)) << 4) + (qg & 7) * 2);
            *(bf16*)(base + so) = hib;
            *(bf16*)(base + 8192 + so) = lob;
        }

        // grid barrier: monotonic ticket counter, no reset, acquire fence after
        __syncthreads();
        if (tid == 0) {
            __threadfence();
            atomicAdd(&g_sync_count, 1);
            const int target = 128 * (t + 1);
            while (atomicAdd(&g_sync_count, 0) < target) __nanosleep(64);
            __threadfence();
        }
        __syncthreads();

        if (prod && t + 1 < TT) {
            const char* An = g_hT[(t + 1) & 1] + (size_t)bm * 16 * 16384;
            MBAR_WAIT(mb + 64, 1u);        // Aempty[0]: count = 8(t+1), even -> passes
            issueA(16 * (t + 1), An);
            MBAR_WAIT(mb + 72, 1u);        // Aempty[1]
            issueA(16 * (t + 1) + 1, An);
            issueXG(t + 1);
        }
    }
}

// ---------------- fp32 SIMT GEMM (head only) ----------------
#define EPI_BIAS 0
#define EPI_RELU 1
template <int BM, int BN, int BK, int TM, int TN, int EPI>
__global__ void gemm_bias_kernel(const float* __restrict__ A,
                                 const float* __restrict__ B,
                                 const float* __restrict__ bias,
                                 float* __restrict__ C,
                                 int M, int N, int K) {
    constexpr int NT = (BM * BN) / (TM * TN);
    __shared__ float As[BK][BM];
    __shared__ float Bs[BK][BN];
    const int tid = threadIdx.x;
    const int bn = blockIdx.x, bm = blockIdx.y;
    const int tx = tid % (BN / TN);
    const int ty = tid / (BN / TN);
    const float* Ab = A + (size_t)bm * BM * K;
    const float* Bb = B + (size_t)bn * BN * K;
    float acc[TM][TN];
#pragma unroll
    for (int i = 0; i < TM; i++)
#pragma unroll
        for (int j = 0; j < TN; j++) acc[i][j] = 0.0f;
    for (int k0 = 0; k0 < K; k0 += BK) {
        constexpr int A4 = BM * BK / 4;
        constexpr int B4 = BN * BK / 4;
#pragma unroll
        for (int i0 = 0; i0 < A4; i0 += NT) {
            int i = i0 + tid;
            int r = i / (BK / 4), c = (i % (BK / 4)) * 4;
            float4 v = *reinterpret_cast<const float4*>(Ab + (size_t)r * K + k0 + c);
            As[c + 0][r] = v.x; As[c + 1][r] = v.y; As[c + 2][r] = v.z; As[c + 3][r] = v.w;
        }
#pragma unroll
        for (int i0 = 0; i0 < B4; i0 += NT) {
            int i = i0 + tid;
            int r = i / (BK / 4), c = (i % (BK / 4)) * 4;
            float4 v = *reinterpret_cast<const float4*>(Bb + (size_t)r * K + k0 + c);
            Bs[c + 0][r] = v.x; Bs[c + 1][r] = v.y; Bs[c + 2][r] = v.z; Bs[c + 3][r] = v.w;
        }
        __syncthreads();
#pragma unroll
        for (int k = 0; k < BK; k++) {
            float ra[TM], rb[TN];
#pragma unroll
            for (int i = 0; i < TM; i += 4) {
                float4 v = *reinterpret_cast<const float4*>(&As[k][ty * TM + i]);
                ra[i] = v.x; ra[i + 1] = v.y; ra[i + 2] = v.z; ra[i + 3] = v.w;
            }
#pragma unroll
            for (int j = 0; j < TN; j += 4) {
                float4 v = *reinterpret_cast<const float4*>(&Bs[k][tx * TN + j]);
                rb[j] = v.x; rb[j + 1] = v.y; rb[j + 2] = v.z; rb[j + 3] = v.w;
            }
#pragma unroll
            for (int i = 0; i < TM; i++)
#pragma unroll
                for (int j = 0; j < TN; j++) acc[i][j] += ra[i] * rb[j];
        }
        __syncthreads();
    }
#pragma unroll
    for (int i = 0; i < TM; i++) {
        int m = bm * BM + ty * TM + i;
#pragma unroll
        for (int j = 0; j < TN; j++) {
            int n = bn * BN + tx * TN + j;
            float v = acc[i][j] + bias[n];
            if (EPI == EPI_RELU) v = fmaxf(v, 0.0f);
            C[(size_t)m * N + n] = v;
        }
    }
}

// ---------------- host ----------------
extern "C" void kernel_launch(void* const* d_in, const int* in_sizes, int n_in,
                              void* d_out, int out_size) {
    const float* x    = (const float*)d_in[0];
    const float* W_ih = (const float*)d_in[1];
    const float* W_hh = (const float*)d_in[2];
    const float* b_ih = (const float*)d_in[3];
    const float* b_hh = (const float*)d_in[4];
    const float* W1   = (const float*)d_in[5];
    const float* b1   = (const float*)d_in[6];
    const float* W2   = (const float*)d_in[7];
    const float* b2   = (const float*)d_in[8];
    float* out = (float*)d_out;

    float* p_hlast;
    cudaGetSymbolAddress((void**)&p_hlast, g_hlast);

    static int attr_set = 0;
    if (!attr_set) {
        cudaFuncSetAttribute(lstm_persistent, cudaFuncAttributeMaxDynamicSharedMemorySize, P_SMEM);
        cudaFuncSetAttribute(xgates_mma_kernel, cudaFuncAttributeMaxDynamicSharedMemorySize, XG_SMEM);
        attr_set = 1;
    }

    // 1) pre-swizzled tiles + state reset (incl. grid-sync counter)
    prep_kernel<<<1024, 256>>>(x, W_ih, W_hh, b_ih, b_hh);

    // 2) x_gates via HMMA + bulk-async
    xgates_mma_kernel<<<dim3(GG / 128, (NB * TT) / 128), 512, XG_SMEM>>>();

    // 3) ALL 128 recurrent steps in one persistent launch
    lstm_persistent<<<dim3(32, 4), 512, P_SMEM>>>();

    // 4) head (fp32 SIMT)
    float* pre_out = out + NB * OUTD;
    gemm_bias_kernel<64, 128, 16, 4, 8, EPI_RELU>
        <<<dim3(HH / 128, NB / 64), 256>>>(p_hlast, W1, b1, pre_out, NB, HH, HH);
    gemm_bias_kernel<64, 128, 16, 4, 8, EPI_BIAS>
        <<<dim3(OUTD / 128, NB / 64), 256>>>(pre_out, W2, b2, out, NB, OUTD, HH);
}